// round 2
// baseline (speedup 1.0000x reference)
#include <cuda_runtime.h>

// Scalar accumulator in device global memory (no allocations allowed).
__device__ double g_acc;

// Turkish similar-char group id: 0 = none.
// Group 1: 'i'(105), 'ı'(305); Group 2: 'o'(111), 'ö'(246);
// Group 3: 'u'(117), 'ü'(252); Group 4: 'g'(103), 'ğ'(287).
__device__ __forceinline__ int grp(int c) {
    switch (c) {
        case 105: case 305: return 1;
        case 111: case 246: return 2;
        case 117: case 252: return 3;
        case 103: case 287: return 4;
        default: return 0;
    }
}

__global__ void zero_acc_kernel() { g_acc = 0.0; }

// One warp per row. V = 512 fixed. Each lane holds 16 floats in registers
// (4x float4), so the row is read from HBM exactly once.
__global__ void __launch_bounds__(256) turkish_loss_kernel(
    const float* __restrict__ pred,
    const int* __restrict__ tgt,      // JAX int64 is int32 on-device (no x64)
    int nrows)
{
    const int lane = threadIdx.x & 31;
    const int warp_in_block = threadIdx.x >> 5;
    const int warps_per_block = blockDim.x >> 5;
    const int gwarp = blockIdx.x * warps_per_block + warp_in_block;
    const int total_warps = gridDim.x * warps_per_block;

    double local = 0.0;

    for (int row = gwarp; row < nrows; row += total_warps) {
        const float4* rp4 = reinterpret_cast<const float4*>(pred + (size_t)row * 512);

        float4 v[4];
        #pragma unroll
        for (int k = 0; k < 4; k++)
            v[k] = rp4[lane + k * 32];   // float idx = lane*4 + k*128

        // ---- max + argmax (first occurrence on ties) ----
        float m = -3.402823466e38f;
        int mi = 0x7fffffff;
        #pragma unroll
        for (int k = 0; k < 4; k++) {
            const float* f = reinterpret_cast<const float*>(&v[k]);
            #pragma unroll
            for (int j = 0; j < 4; j++) {
                int idx = k * 128 + lane * 4 + j;
                float x = f[j];
                if (x > m || (x == m && idx < mi)) { m = x; mi = idx; }
            }
        }
        #pragma unroll
        for (int off = 16; off > 0; off >>= 1) {
            float om = __shfl_down_sync(0xffffffffu, m, off);
            int   oi = __shfl_down_sync(0xffffffffu, mi, off);
            if (om > m || (om == m && oi < mi)) { m = om; mi = oi; }
        }
        m  = __shfl_sync(0xffffffffu, m, 0);
        mi = __shfl_sync(0xffffffffu, mi, 0);

        // ---- sum of exp(x - m) from the same registers ----
        float s = 0.0f;
        #pragma unroll
        for (int k = 0; k < 4; k++) {
            const float* f = reinterpret_cast<const float*>(&v[k]);
            #pragma unroll
            for (int j = 0; j < 4; j++)
                s += __expf(f[j] - m);
        }
        #pragma unroll
        for (int off = 16; off > 0; off >>= 1)
            s += __shfl_down_sync(0xffffffffu, s, off);

        if (lane == 0) {
            int t = tgt[row];
            // Safety clamp: an unexpected dtype shows up as rel_err, never a crash.
            t = min(max(t, 0), 511);
            float xt = __ldg(pred + (size_t)row * 512 + t);  // L1/L2 hit
            float loss = m + __logf(s) - xt;                  // -log_softmax[t]
            int gp = grp(mi);
            int gt = grp(t);
            float scale = (gp > 0 && gp == gt) ? 0.8f : 1.0f;
            local += (double)(loss * scale);
        }
    }

    // ---- block reduction, one atomic per block ----
    __shared__ double sacc[8];
    if (lane == 0) sacc[warp_in_block] = local;
    __syncthreads();
    if (threadIdx.x == 0) {
        double b = 0.0;
        #pragma unroll
        for (int w = 0; w < 8; w++) b += sacc[w];
        atomicAdd(&g_acc, b);
    }
}

__global__ void finalize_kernel(float* out, int nrows) {
    out[0] = (float)(g_acc / (double)nrows);
}

extern "C" void kernel_launch(void* const* d_in, const int* in_sizes, int n_in,
                              void* d_out, int out_size)
{
    const float* pred = (const float*)d_in[0];
    const int* tgt = (const int*)d_in[1];
    float* out = (float*)d_out;

    const int nrows = in_sizes[1];          // 524288

    zero_acc_kernel<<<1, 1>>>();

    const int threads = 256;                // 8 warps/block
    const int blocks = 2048;                // 16384 warps, grid-stride over rows
    turkish_loss_kernel<<<blocks, threads>>>(pred, tgt, nrows);

    finalize_kernel<<<1, 1>>>(out, nrows);
}

// round 3
// speedup vs baseline: 1.0835x; 1.0835x over previous
#include <cuda_runtime.h>

// Accumulator + completion counter in device globals (no allocations allowed).
__device__ double g_acc = 0.0;
__device__ unsigned int g_count = 0;

// Turkish similar-char group id: 0 = none.
// 1: i(105), ı(305); 2: o(111), ö(246); 3: u(117), ü(252); 4: g(103), ğ(287).
__device__ __forceinline__ int grp(int c) {
    switch (c) {
        case 105: case 305: return 1;
        case 111: case 246: return 2;
        case 117: case 252: return 3;
        case 103: case 287: return 4;
        default: return 0;
    }
}

// Per-row computation given the row resident in registers (4x float4 per lane).
// Returns the scaled loss (valid in lane 0; harmless elsewhere).
__device__ __forceinline__ float row_loss(const float4 (&v)[4], int lane,
                                          float xt, int t)
{
    // ---- lane-local max + argmax (increasing idx order => first occurrence) ----
    float m = -3.402823466e38f;
    int mi = 0;
    #pragma unroll
    for (int k = 0; k < 4; k++) {
        const float* f = reinterpret_cast<const float*>(&v[k]);
        #pragma unroll
        for (int j = 0; j < 4; j++) {
            int idx = k * 128 + lane * 4 + j;
            float x = f[j];
            if (x > m) { m = x; mi = idx; }
        }
    }

    // ---- lane-local exp-sum with the LANE max (no shuffle dependency) ----
    float s = 0.0f;
    #pragma unroll
    for (int k = 0; k < 4; k++) {
        const float* f = reinterpret_cast<const float*>(&v[k]);
        #pragma unroll
        for (int j = 0; j < 4; j++)
            s += __expf(f[j] - m);
    }

    // ---- single fused bfly reduce: (max, sum, argmax) together ----
    #pragma unroll
    for (int off = 16; off > 0; off >>= 1) {
        float m2 = __shfl_xor_sync(0xffffffffu, m, off);
        float s2 = __shfl_xor_sync(0xffffffffu, s, off);
        int  mi2 = __shfl_xor_sync(0xffffffffu, mi, off);
        float M = fmaxf(m, m2);
        s = s * __expf(m - M) + s2 * __expf(m2 - M);
        bool take = (m2 > m) || (m2 == m && mi2 < mi);
        mi = take ? mi2 : mi;
        m = M;
    }
    // all lanes now hold (m = global max, s = global sum, mi = argmax)

    float loss = m + __logf(s) - xt;          // -log_softmax[t]
    int gp = grp(mi);
    int gt = grp(t);
    float scale = (gp > 0 && gp == gt) ? 0.8f : 1.0f;
    return loss * scale;
}

__global__ void __launch_bounds__(256) turkish_loss_kernel(
    const float* __restrict__ pred,
    const int* __restrict__ tgt,
    float* __restrict__ out,
    int nrows)
{
    const int lane = threadIdx.x & 31;
    const int warp_in_block = threadIdx.x >> 5;
    const int gwarp = blockIdx.x * 8 + warp_in_block;
    const int stride = gridDim.x * 8;

    double local = 0.0;

    for (int rowA = gwarp; rowA < nrows; rowA += 2 * stride) {
        const int rowB = rowA + stride;
        const bool hasB = rowB < nrows;

        // Early target + target-logit prefetch (lane 0 only; long dependent
        // chain issued before the bulk loads so it hides under them).
        int tA = 0, tB = 0;
        float xtA = 0.0f, xtB = 0.0f;
        if (lane == 0) {
            tA = min(max(__ldg(tgt + rowA), 0), 511);
            xtA = __ldg(pred + (size_t)rowA * 512 + tA);
            if (hasB) {
                tB = min(max(__ldg(tgt + rowB), 0), 511);
                xtB = __ldg(pred + (size_t)rowB * 512 + tB);
            }
        }

        // Bulk loads for both rows (8 LDG.128 in flight per lane).
        const float4* pA = reinterpret_cast<const float4*>(pred + (size_t)rowA * 512);
        const float4* pB = reinterpret_cast<const float4*>(pred + (size_t)(hasB ? rowB : rowA) * 512);
        float4 vA[4], vB[4];
        #pragma unroll
        for (int k = 0; k < 4; k++) vA[k] = pA[lane + k * 32];
        #pragma unroll
        for (int k = 0; k < 4; k++) vB[k] = pB[lane + k * 32];

        float lA = row_loss(vA, lane, xtA, tA);
        if (lane == 0) local += (double)lA;
        if (hasB) {
            float lB = row_loss(vB, lane, xtB, tB);
            if (lane == 0) local += (double)lB;
        }
    }

    // ---- block reduction ----
    __shared__ double sacc[8];
    if (lane == 0) sacc[warp_in_block] = local;
    __syncthreads();

    if (threadIdx.x == 0) {
        double b = 0.0;
        #pragma unroll
        for (int w = 0; w < 8; w++) b += sacc[w];
        atomicAdd(&g_acc, b);
        __threadfence();
        unsigned int old = atomicAdd(&g_count, 1u);
        if (old == gridDim.x - 1) {
            // last block: all g_acc contributions are visible
            double tot = atomicAdd(&g_acc, 0.0);
            out[0] = (float)(tot / (double)nrows);
            // reset for the next graph replay (deterministic)
            g_acc = 0.0;
            g_count = 0u;
            __threadfence();
        }
    }
}

extern "C" void kernel_launch(void* const* d_in, const int* in_sizes, int n_in,
                              void* d_out, int out_size)
{
    const float* pred = (const float*)d_in[0];
    const int* tgt = (const int*)d_in[1];
    float* out = (float*)d_out;

    const int nrows = in_sizes[1];          // 524288

    const int threads = 256;                // 8 warps/block
    const int blocks = 2048;                // 16384 warps, 2-row batched grid stride
    turkish_loss_kernel<<<blocks, threads>>>(pred, tgt, out, nrows);
}

// round 4
// speedup vs baseline: 1.3175x; 1.2160x over previous
#include <cuda_runtime.h>

// Accumulator + completion counter in device globals (no allocations allowed).
__device__ double g_acc = 0.0;
__device__ unsigned int g_count = 0;

// Turkish similar-char group id: 0 = none.
// 1: i(105), ı(305); 2: o(111), ö(246); 3: u(117), ü(252); 4: g(103), ğ(287).
__device__ __forceinline__ int grp(int c) {
    switch (c) {
        case 105: case 305: return 1;
        case 111: case 246: return 2;
        case 117: case 252: return 3;
        case 103: case 287: return 4;
        default: return 0;
    }
}

// HW warp reductions (single SASS REDUX, sm_80+).
__device__ __forceinline__ unsigned redux_max_u32(unsigned v) {
    unsigned r;
    asm("redux.sync.max.u32 %0, %1, 0xffffffff;" : "=r"(r) : "r"(v));
    return r;
}
__device__ __forceinline__ int redux_min_s32(int v) {
    int r;
    asm("redux.sync.min.s32 %0, %1, 0xffffffff;" : "=r"(r) : "r"(v));
    return r;
}

// Order-preserving float->u32 (works for all finite floats incl. negatives).
__device__ __forceinline__ unsigned f2ord(float f) {
    unsigned u = __float_as_uint(f);
    return ((int)u < 0) ? ~u : (u | 0x80000000u);
}
__device__ __forceinline__ float ord2f(unsigned u) {
    u = (u & 0x80000000u) ? (u ^ 0x80000000u) : ~u;
    return __uint_as_float(u);
}

// Per-row computation with the row resident in registers (4x float4 per lane).
// Returns scaled loss (same value in all lanes; lane 0 accumulates).
__device__ __forceinline__ float row_loss(const float4 (&v)[4], int lane,
                                          float xt, int t)
{
    const float* f = reinterpret_cast<const float*>(&v[0]);

    // ---- lane max: FMNMX tree (no index tracking needed) ----
    float a0 = fmaxf(f[0], f[1]),  a1 = fmaxf(f[2], f[3]);
    float a2 = fmaxf(f[4], f[5]),  a3 = fmaxf(f[6], f[7]);
    float a4 = fmaxf(f[8], f[9]),  a5 = fmaxf(f[10], f[11]);
    float a6 = fmaxf(f[12], f[13]), a7 = fmaxf(f[14], f[15]);
    float b0 = fmaxf(a0, a1), b1 = fmaxf(a2, a3);
    float b2 = fmaxf(a4, a5), b3 = fmaxf(a6, a7);
    float mlane = fmaxf(fmaxf(b0, b1), fmaxf(b2, b3));

    // ---- global max in ONE instruction ----
    float M = ord2f(redux_max_u32(f2ord(mlane)));

    // ---- first-occurrence argmax: lane scan (descending overwrite) + redux.min ----
    int cand = 0x7fffffff;
    #pragma unroll
    for (int e = 15; e >= 0; e--) {
        int idx = (e >> 2) * 128 + lane * 4 + (e & 3);
        if (f[e] == M) cand = idx;
    }
    int mi = redux_min_s32(cand);

    // ---- exp sum with GLOBAL max: exp2(x*log2e - M*log2e), FFMA+MUFU each ----
    const float L2E = 1.4426950408889634f;
    const float c = -M * L2E;
    float e0 = exp2f(fmaf(f[0], L2E, c)) + exp2f(fmaf(f[1], L2E, c));
    float e1 = exp2f(fmaf(f[2], L2E, c)) + exp2f(fmaf(f[3], L2E, c));
    float e2 = exp2f(fmaf(f[4], L2E, c)) + exp2f(fmaf(f[5], L2E, c));
    float e3 = exp2f(fmaf(f[6], L2E, c)) + exp2f(fmaf(f[7], L2E, c));
    float e4 = exp2f(fmaf(f[8], L2E, c)) + exp2f(fmaf(f[9], L2E, c));
    float e5 = exp2f(fmaf(f[10], L2E, c)) + exp2f(fmaf(f[11], L2E, c));
    float e6 = exp2f(fmaf(f[12], L2E, c)) + exp2f(fmaf(f[13], L2E, c));
    float e7 = exp2f(fmaf(f[14], L2E, c)) + exp2f(fmaf(f[15], L2E, c));
    float s = ((e0 + e1) + (e2 + e3)) + ((e4 + e5) + (e6 + e7));

    // ---- float sum across lanes (redux has no f32 add): 5x shfl+add ----
    #pragma unroll
    for (int off = 16; off > 0; off >>= 1)
        s += __shfl_xor_sync(0xffffffffu, s, off);

    float loss = M + __logf(s) - xt;            // -log_softmax[t]
    int gp = grp(mi);
    int gt = grp(t);
    float scale = (gp > 0 && gp == gt) ? 0.8f : 1.0f;
    return loss * scale;
}

__global__ void __launch_bounds__(256) turkish_loss_kernel(
    const float* __restrict__ pred,
    const int* __restrict__ tgt,
    float* __restrict__ out,
    int nrows)
{
    const int lane = threadIdx.x & 31;
    const int warp_in_block = threadIdx.x >> 5;
    const int gwarp = blockIdx.x * 8 + warp_in_block;
    const int stride = gridDim.x * 8;

    double local = 0.0;

    for (int rowA = gwarp; rowA < nrows; rowA += 2 * stride) {
        const int rowB = rowA + stride;
        const bool hasB = rowB < nrows;

        // Target + target-logit fetch (lane 0), issued before the bulk loads.
        int tA = 0, tB = 0;
        float xtA = 0.0f, xtB = 0.0f;
        if (lane == 0) {
            tA = min(max(__ldg(tgt + rowA), 0), 511);
            xtA = __ldg(pred + (size_t)rowA * 512 + tA);
            if (hasB) {
                tB = min(max(__ldg(tgt + rowB), 0), 511);
                xtB = __ldg(pred + (size_t)rowB * 512 + tB);
            }
        }

        // Bulk loads for both rows (8 LDG.128 in flight per lane).
        const float4* pA = reinterpret_cast<const float4*>(pred + (size_t)rowA * 512);
        const float4* pB = reinterpret_cast<const float4*>(pred + (size_t)(hasB ? rowB : rowA) * 512);
        float4 vA[4], vB[4];
        #pragma unroll
        for (int k = 0; k < 4; k++) vA[k] = pA[lane + k * 32];
        #pragma unroll
        for (int k = 0; k < 4; k++) vB[k] = pB[lane + k * 32];

        float lA = row_loss(vA, lane, xtA, tA);
        if (lane == 0) local += (double)lA;
        if (hasB) {
            float lB = row_loss(vB, lane, xtB, tB);
            if (lane == 0) local += (double)lB;
        }
    }

    // ---- block reduction, one atomic per block ----
    __shared__ double sacc[8];
    if (lane == 0) sacc[warp_in_block] = local;
    __syncthreads();

    if (threadIdx.x == 0) {
        double b = 0.0;
        #pragma unroll
        for (int w = 0; w < 8; w++) b += sacc[w];
        atomicAdd(&g_acc, b);
        __threadfence();
        unsigned int old = atomicAdd(&g_count, 1u);
        if (old == gridDim.x - 1) {
            double tot = atomicAdd(&g_acc, 0.0);
            out[0] = (float)(tot / (double)nrows);
            g_acc = 0.0;                // reset for next graph replay
            g_count = 0u;
            __threadfence();
        }
    }
}

extern "C" void kernel_launch(void* const* d_in, const int* in_sizes, int n_in,
                              void* d_out, int out_size)
{
    const float* pred = (const float*)d_in[0];
    const int* tgt = (const int*)d_in[1];
    float* out = (float*)d_out;

    const int nrows = in_sizes[1];          // 524288

    const int threads = 256;                // 8 warps/block
    const int blocks = 2048;
    turkish_loss_kernel<<<blocks, threads>>>(pred, tgt, out, nrows);
}